// round 15
// baseline (speedup 1.0000x reference)
#include <cuda_runtime.h>
#include <cuda_bf16.h>
#include <math.h>
#include <stdint.h>

#define SEQ   2048
#define NH    32
#define HD    64
#define HIDD  2048
#define NB    2
#define NQKV  (3 * NH * HD)   // 6144
#define MROWS (NB * SEQ)      // 4096

// ---------------------------------------------------------------------------
// Scratch (__device__ globals per harness rules — no cudaMalloc anywhere)
// ---------------------------------------------------------------------------
__device__ float g_qkv[(size_t)MROWS * NQKV];
__device__ int   g_mask_u8;
__device__ __nv_bfloat16 g_bias[(size_t)NB * SEQ * SEQ];     // 0/1 mask as bf16
// GEMM decomposition buffers (x reused: hidden, then attn written by flash)
__device__ __nv_bfloat16 g_xhi[(size_t)MROWS * HIDD];
__device__ __nv_bfloat16 g_xlo[(size_t)MROWS * HIDD];
__device__ __nv_bfloat16 g_whi[(size_t)NQKV * HIDD];
__device__ __nv_bfloat16 g_wlo[(size_t)NQKV * HIDD];
// Attention operands, bf16 hi/lo
__device__ __nv_bfloat16 g_Qhi[(size_t)NB * NH * SEQ * HD];  // [B,H,S,D], scaled 1/8
__device__ __nv_bfloat16 g_Qlo[(size_t)NB * NH * SEQ * HD];
__device__ __nv_bfloat16 g_Khi[(size_t)NB * NH * SEQ * HD];
__device__ __nv_bfloat16 g_Klo[(size_t)NB * NH * SEQ * HD];
__device__ __nv_bfloat16 g_Vthi[(size_t)NB * NH * HD * SEQ]; // [B,H,D,S]
__device__ __nv_bfloat16 g_Vtlo[(size_t)NB * NH * HD * SEQ];

// ---------------------------------------------------------------------------
// Helpers (portable PTX: sm_80+)
// ---------------------------------------------------------------------------
__device__ __forceinline__ uint32_t smem_u32(const void* p) {
    uint32_t a;
    asm("{ .reg .u64 t; cvta.to.shared.u64 t, %1; cvt.u32.u64 %0, t; }"
        : "=r"(a) : "l"(p));
    return a;
}

__device__ __forceinline__ void ldsm4(uint32_t addr, uint32_t* r) {
    asm volatile("ldmatrix.sync.aligned.m8n8.x4.shared.b16 {%0,%1,%2,%3}, [%4];"
                 : "=r"(r[0]), "=r"(r[1]), "=r"(r[2]), "=r"(r[3]) : "r"(addr));
}

__device__ __forceinline__ void mma16816(float* c, const uint32_t* a,
                                         uint32_t b0, uint32_t b1) {
    asm volatile(
        "mma.sync.aligned.m16n8k16.row.col.f32.bf16.bf16.f32 "
        "{%0,%1,%2,%3}, {%4,%5,%6,%7}, {%8,%9}, {%0,%1,%2,%3};"
        : "+f"(c[0]), "+f"(c[1]), "+f"(c[2]), "+f"(c[3])
        : "r"(a[0]), "r"(a[1]), "r"(a[2]), "r"(a[3]), "r"(b0), "r"(b1));
}

__device__ __forceinline__ void cp16(uint32_t dst, const void* src) {
    asm volatile("cp.async.cg.shared.global [%0], [%1], 16;"
                 :: "r"(dst), "l"(src));
}

// Fast exp on the FMA pipe. x <= 0; ~1e-7 rel.
__device__ __forceinline__ float fexp(float x) {
    x = fmaxf(x, -80.f);
    float t = fmaf(x, 1.4426950408889634f, 12582912.f);
    float n = t - 12582912.f;
    float f = fmaf(x, 1.4426950408889634f, -n);
    float p = 1.8775767e-3f;
    p = fmaf(p, f, 8.9893397e-3f);
    p = fmaf(p, f, 5.5826318e-2f);
    p = fmaf(p, f, 2.4015361e-1f);
    p = fmaf(p, f, 6.9315308e-1f);
    p = fmaf(p, f, 1.0f);
    return __int_as_float(__float_as_int(p) + (__float_as_int(t) << 23));
}

__device__ __forceinline__ void pack3(float f0, float f1, uint32_t& rh, uint32_t& rl) {
    __nv_bfloat16 h0 = __float2bfloat16(f0), h1 = __float2bfloat16(f1);
    __nv_bfloat16 l0 = __float2bfloat16(f0 - __bfloat162float(h0));
    __nv_bfloat16 l1 = __float2bfloat16(f1 - __bfloat162float(h1));
    __nv_bfloat162 H = __halves2bfloat162(h0, h1);
    __nv_bfloat162 L = __halves2bfloat162(l0, l1);
    rh = *(uint32_t*)&H;
    rl = *(uint32_t*)&L;
}

// ---------------------------------------------------------------------------
// Decompose fp32 -> bf16 hi + lo
// ---------------------------------------------------------------------------
__global__ __launch_bounds__(256) void decompose_kernel(
        const float4* __restrict__ x, __nv_bfloat162* __restrict__ hi,
        __nv_bfloat162* __restrict__ lo, int n4) {
    int i = blockIdx.x * blockDim.x + threadIdx.x;
    if (i >= n4) return;
    float4 v = x[i];
    __nv_bfloat16 h0 = __float2bfloat16(v.x), h1 = __float2bfloat16(v.y);
    __nv_bfloat16 h2 = __float2bfloat16(v.z), h3 = __float2bfloat16(v.w);
    __nv_bfloat16 l0 = __float2bfloat16(v.x - __bfloat162float(h0));
    __nv_bfloat16 l1 = __float2bfloat16(v.y - __bfloat162float(h1));
    __nv_bfloat16 l2 = __float2bfloat16(v.z - __bfloat162float(h2));
    __nv_bfloat16 l3 = __float2bfloat16(v.w - __bfloat162float(h3));
    hi[2 * i]     = __halves2bfloat162(h0, h1);
    hi[2 * i + 1] = __halves2bfloat162(h2, h3);
    lo[2 * i]     = __halves2bfloat162(l0, l1);
    lo[2 * i + 1] = __halves2bfloat162(l2, l3);
}

// ---------------------------------------------------------------------------
// Mask detection + conversion to bf16 0/1 bias array
// ---------------------------------------------------------------------------
__global__ void detect_mask_kernel(const unsigned char* __restrict__ m) {
    __shared__ int found;
    if (threadIdx.x == 0) found = 0;
    __syncthreads();
    const uint4* p = (const uint4*)m;
    int f = 0;
    for (int i = threadIdx.x; i < 65536; i += blockDim.x) {
        uint4 w = p[i];
        unsigned ws[4] = {w.x, w.y, w.z, w.w};
#pragma unroll
        for (int j = 0; j < 4; ++j) {
            unsigned v = ws[j];
            if (((v >> 8) & 0xFFu) == 1u || ((v >> 16) & 0xFFu) == 1u ||
                ((v >> 24) & 0xFFu) == 1u)
                f = 1;
        }
    }
    if (f) atomicOr(&found, 1);
    __syncthreads();
    if (threadIdx.x == 0) g_mask_u8 = found;
}

__global__ __launch_bounds__(256) void mask_bias_kernel(const unsigned char* __restrict__ m) {
    const size_t i = ((size_t)blockIdx.x * blockDim.x + threadIdx.x) * 8;
    const __nv_bfloat16 one = __float2bfloat16(1.f);
    const __nv_bfloat16 zero = __float2bfloat16(0.f);
    __nv_bfloat16 o[8];
    if (g_mask_u8) {
        uint2 w = *(const uint2*)(m + i);
        unsigned a0 = w.x, a1 = w.y;
#pragma unroll
        for (int j = 0; j < 4; ++j) {
            o[j]     = ((a0 >> (j * 8)) & 0xFFu) ? one : zero;
            o[j + 4] = ((a1 >> (j * 8)) & 0xFFu) ? one : zero;
        }
    } else {
        const unsigned* p = (const unsigned*)m + i;
        uint4 w0 = *(const uint4*)p;
        uint4 w1 = *(const uint4*)(p + 4);
        o[0] = w0.x ? one : zero; o[1] = w0.y ? one : zero;
        o[2] = w0.z ? one : zero; o[3] = w0.w ? one : zero;
        o[4] = w1.x ? one : zero; o[5] = w1.y ? one : zero;
        o[6] = w1.z ? one : zero; o[7] = w1.w ? one : zero;
    }
    *(uint4*)&g_bias[i] = *(uint4*)o;
}

// ---------------------------------------------------------------------------
// Projection GEMM: bf16x3 HMMA, 4-stage cp.async pipeline, BK=16,
// one __syncthreads per K-iter. 128x128 CTA tile, 8 warps (2m x 4n), 64x32 each.
// ---------------------------------------------------------------------------
#define SSTR16 24
#define A16_B  (128 * SSTR16 * 2)     // 6144 B per array
#define STG16_B (4 * A16_B)           // 24576 B per stage
#define GEMM_SMEM (4 * STG16_B)       // 98304 B

__global__ __launch_bounds__(256, 2) void hmma_gemm(
        const __nv_bfloat16* __restrict__ Ah, const __nv_bfloat16* __restrict__ Al,
        const __nv_bfloat16* __restrict__ Bh, const __nv_bfloat16* __restrict__ Bl,
        float* __restrict__ C, int K, int N) {
    extern __shared__ char gsm[];
    const uint32_t ub = smem_u32(gsm);

    const int tid = threadIdx.x;
    const int wid = tid >> 5;
    const int lane = tid & 31;
    const int warp_m = wid & 1;
    const int warp_n = wid >> 1;
    const int m0 = blockIdx.y * 128, n0 = blockIdx.x * 128;

    const int lr = tid >> 1;            // 0..127
    const int ls8 = (tid & 1) * 8;      // 0 / 8 elems
    const __nv_bfloat16* pAh = Ah + (size_t)(m0 + lr) * K + ls8;
    const __nv_bfloat16* pAl = Al + (size_t)(m0 + lr) * K + ls8;
    const __nv_bfloat16* pBh = Bh + (size_t)(n0 + lr) * K + ls8;
    const __nv_bfloat16* pBl = Bl + (size_t)(n0 + lr) * K + ls8;
    const uint32_t so = (uint32_t)(lr * SSTR16 + ls8) * 2;

    const int a_row = lane & 15;
    const int a_col = (lane >> 4) << 3;
    const int b_n   = (lane & 7) + ((lane & 16) ? 8 : 0);
    const int b_k   = (lane & 8) ? 8 : 0;

    float acc[4][4][4];
#pragma unroll
    for (int i = 0; i < 4; ++i)
#pragma unroll
        for (int j = 0; j < 4; ++j)
#pragma unroll
            for (int v = 0; v < 4; ++v) acc[i][j][v] = 0.f;

    const int kIters = K >> 4;

    auto issue = [&](int it, int st) {
        const int k0 = it << 4;
        uint32_t d = ub + st * STG16_B + so;
        cp16(d,              pAh + k0);
        cp16(d + A16_B,      pAl + k0);
        cp16(d + 2 * A16_B,  pBh + k0);
        cp16(d + 3 * A16_B,  pBl + k0);
        asm volatile("cp.async.commit_group;" ::: "memory");
    };

    issue(0, 0); issue(1, 1); issue(2, 2);

    for (int it = 0; it < kIters; ++it) {
        asm volatile("cp.async.wait_group 2;" ::: "memory");
        __syncthreads();
        if (it + 3 < kIters) issue(it + 3, (it + 3) & 3);
        else asm volatile("cp.async.commit_group;" ::: "memory");

        const uint32_t uAh = ub + (it & 3) * STG16_B;
        const uint32_t uAl = uAh + A16_B;
        const uint32_t uBh = uAh + 2 * A16_B;
        const uint32_t uBl = uAh + 3 * A16_B;

        uint32_t bh[2][4], bl[2][4];
#pragma unroll
        for (int np = 0; np < 2; ++np) {
            uint32_t boff = (uint32_t)(((warp_n * 32 + np * 16 + b_n) * SSTR16 + b_k) * 2);
            ldsm4(uBh + boff, bh[np]);
            ldsm4(uBl + boff, bl[np]);
        }
#pragma unroll
        for (int mt = 0; mt < 4; ++mt) {
            uint32_t aoff = (uint32_t)(((warp_m * 64 + mt * 16 + a_row) * SSTR16 + a_col) * 2);
            uint32_t ahf[4], alf[4];
            ldsm4(uAh + aoff, ahf);
            ldsm4(uAl + aoff, alf);
#pragma unroll
            for (int nt = 0; nt < 4; ++nt) {
                uint32_t b0h = bh[nt >> 1][(nt & 1) * 2];
                uint32_t b1h = bh[nt >> 1][(nt & 1) * 2 + 1];
                uint32_t b0l = bl[nt >> 1][(nt & 1) * 2];
                uint32_t b1l = bl[nt >> 1][(nt & 1) * 2 + 1];
                mma16816(acc[mt][nt], ahf, b0h, b1h);
                mma16816(acc[mt][nt], alf, b0h, b1h);
                mma16816(acc[mt][nt], ahf, b0l, b1l);
            }
        }
    }

#pragma unroll
    for (int mt = 0; mt < 4; ++mt) {
#pragma unroll
        for (int nt = 0; nt < 4; ++nt) {
            int r = m0 + warp_m * 64 + mt * 16 + (lane >> 2);
            int c = n0 + warp_n * 32 + nt * 8 + (lane & 3) * 2;
            float2 lo = make_float2(acc[mt][nt][0], acc[mt][nt][1]);
            float2 hi = make_float2(acc[mt][nt][2], acc[mt][nt][3]);
            *(float2*)(C + (size_t)r * N + c) = lo;
            *(float2*)(C + (size_t)(r + 8) * N + c) = hi;
        }
    }
}

// ---------------------------------------------------------------------------
// RoPE + split + bf16 hi/lo decomposition. Q scaled by 1/8. V transposed.
// ---------------------------------------------------------------------------
__device__ __forceinline__ void wr_hl(__nv_bfloat16* hi, __nv_bfloat16* lo,
                                      size_t off, float v) {
    __nv_bfloat16 h = __float2bfloat16(v);
    hi[off] = h;
    lo[off] = __float2bfloat16(v - __bfloat162float(h));
}

__global__ __launch_bounds__(256) void rope_scatter(const float* __restrict__ qkv,
                                                    const int* __restrict__ pos_ids) {
    int idx = blockIdx.x * blockDim.x + threadIdx.x;
    int d = idx & 31;
    int h = (idx >> 5) & (NH - 1);
    int s = (idx >> 10) & (SEQ - 1);
    int b = idx >> 21;
    int pos = pos_ids[b * SEQ + s];

    const float* src = qkv + (size_t)(b * SEQ + s) * NQKV + h * (3 * HD);
    float q1 = src[d],       q2 = src[d + 32];
    float k1 = src[64 + d],  k2 = src[96 + d];
    float v1 = src[128 + d], v2 = src[160 + d];

    float invf = (float)pow(10000.0, -(double)d / 32.0);
    float t = (float)pos * invf;
    float sn = (float)sin((double)t);
    float cs = (float)cos((double)t);

    const float qs = 0.125f;
    size_t qk = ((size_t)(b * NH + h) * SEQ + s) * HD;
    wr_hl(g_Qhi, g_Qlo, qk + d,      (q1 * cs - q2 * sn) * qs);
    wr_hl(g_Qhi, g_Qlo, qk + d + 32, (q2 * cs + q1 * sn) * qs);
    wr_hl(g_Khi, g_Klo, qk + d,      k1 * cs - k2 * sn);
    wr_hl(g_Khi, g_Klo, qk + d + 32, k2 * cs + k1 * sn);
    size_t vt = ((size_t)(b * NH + h) * HD + d) * SEQ + s;
    wr_hl(g_Vthi, g_Vtlo, vt,                 v1);
    wr_hl(g_Vthi, g_Vtlo, vt + 32 * SEQ,      v2);
}

// ---------------------------------------------------------------------------
// Flash attention via bf16x3 HMMA, 2-stage cp.async pipeline.
// Block = (b, h, 64 q rows), 4 warps x m16.
// Stage: Kh, Kl, Vh, Vl, Bias(bf16) each [64][72] bf16 = 9216 B -> 46080/stage.
// ---------------------------------------------------------------------------
#define FSTR 72
#define AF_B (64 * FSTR * 2)          // 9216
#define STGF_B (5 * AF_B)             // 46080
#define FLASH_SMEM (2 * STGF_B)       // 92160

__global__ __launch_bounds__(128) void flash_hmma() {
    extern __shared__ char fsm[];
    const uint32_t ufb = smem_u32(fsm);

    const int q0 = blockIdx.x * 64;
    const int h  = blockIdx.y;
    const int b  = blockIdx.z;
    const int tid = threadIdx.x;
    const int wid = tid >> 5;
    const int lane = tid & 31;

    const size_t hb = (size_t)(b * NH + h) * SEQ;
    const size_t vb = (size_t)(b * NH + h) * HD;

    const int lrow = tid >> 1;
    const int lhalf = (tid & 1) * 32;

    // ---- Stage Q synchronously into stage-0 Kh/Kl region, extract frags ----
    {
        const __nv_bfloat16* qh_src = g_Qhi + (hb + q0 + lrow) * HD + lhalf;
        const __nv_bfloat16* ql_src = g_Qlo + (hb + q0 + lrow) * HD + lhalf;
        __nv_bfloat16* dh = (__nv_bfloat16*)fsm + lrow * FSTR + lhalf;
        __nv_bfloat16* dl = (__nv_bfloat16*)(fsm + AF_B) + lrow * FSTR + lhalf;
#pragma unroll
        for (int j = 0; j < 4; ++j) {
            *(uint4*)(dh + j * 8) = *(const uint4*)(qh_src + j * 8);
            *(uint4*)(dl + j * 8) = *(const uint4*)(ql_src + j * 8);
        }
    }
    __syncthreads();

    const int a_row = lane & 15;
    const int a_col = (lane >> 4) << 3;
    const int b_n   = (lane & 7) + ((lane & 16) ? 8 : 0);
    const int b_k   = (lane & 8) ? 8 : 0;

    uint32_t qh[4][4], ql[4][4];
#pragma unroll
    for (int kc = 0; kc < 4; ++kc) {
        uint32_t off = (uint32_t)(((wid * 16 + a_row) * FSTR + kc * 16 + a_col) * 2);
        ldsm4(ufb + off, qh[kc]);
        ldsm4(ufb + AF_B + off, ql[kc]);
    }
    __syncthreads();   // Q reads done; stage 0 may be overwritten by cp.async

    const int r0 = lane >> 2;
    const int c2 = (lane & 3) * 2;

    float rm0 = -1e30f, rm1 = -1e30f, l0 = 0.f, l1 = 0.f;
    float o[8][4];
#pragma unroll
    for (int jd = 0; jd < 8; ++jd)
#pragma unroll
        for (int v = 0; v < 4; ++v) o[jd][v] = 0.f;

    const uint32_t so = (uint32_t)(lrow * FSTR + lhalf) * 2;

    auto issue_f = [&](int it, int st) {
        const int k0 = it << 6;
        const __nv_bfloat16* kh = g_Khi + (hb + k0 + lrow) * HD + lhalf;
        const __nv_bfloat16* kl = g_Klo + (hb + k0 + lrow) * HD + lhalf;
        const __nv_bfloat16* vh = g_Vthi + (vb + lrow) * SEQ + k0 + lhalf;
        const __nv_bfloat16* vl = g_Vtlo + (vb + lrow) * SEQ + k0 + lhalf;
        const __nv_bfloat16* bi = g_bias + ((size_t)b * SEQ + q0 + lrow) * SEQ + k0 + lhalf;
        uint32_t d = ufb + st * STGF_B + so;
#pragma unroll
        for (int j = 0; j < 4; ++j) {
            cp16(d + j * 16,              kh + j * 8);
            cp16(d + AF_B + j * 16,       kl + j * 8);
            cp16(d + 2 * AF_B + j * 16,   vh + j * 8);
            cp16(d + 3 * AF_B + j * 16,   vl + j * 8);
            cp16(d + 4 * AF_B + j * 16,   bi + j * 8);
        }
        asm volatile("cp.async.commit_group;" ::: "memory");
    };

    issue_f(0, 0);

    const int nTiles = SEQ / 64;
    for (int it = 0; it < nTiles; ++it) {
        const int st = it & 1;
        if (it + 1 < nTiles) {
            issue_f(it + 1, st ^ 1);
            asm volatile("cp.async.wait_group 1;" ::: "memory");
        } else {
            asm volatile("cp.async.wait_group 0;" ::: "memory");
        }
        __syncthreads();

        const uint32_t uKh = ufb + st * STGF_B;
        const uint32_t uKl = uKh + AF_B;
        const uint32_t uVh = uKh + 2 * AF_B;
        const uint32_t uVl = uKh + 3 * AF_B;
        const __nv_bfloat16* sB = (const __nv_bfloat16*)(fsm + st * STGF_B + 4 * AF_B);

        // ---- S = Q K^T (bf16x3) ----
        float sc[8][4];
#pragma unroll
        for (int j = 0; j < 8; ++j)
#pragma unroll
            for (int v = 0; v < 4; ++v) sc[j][v] = 0.f;
#pragma unroll
        for (int jp = 0; jp < 4; ++jp) {
#pragma unroll
            for (int np = 0; np < 4; ++np) {
                uint32_t off = (uint32_t)(((np * 16 + b_n) * FSTR + jp * 16 + b_k) * 2);
                uint32_t kh[4], kl[4];
                ldsm4(uKh + off, kh);
                ldsm4(uKl + off, kl);
#pragma unroll
                for (int nt = 0; nt < 2; ++nt) {
                    int j = np * 2 + nt;
                    mma16816(sc[j], qh[jp], kh[nt * 2], kh[nt * 2 + 1]);
                    mma16816(sc[j], ql[jp], kh[nt * 2], kh[nt * 2 + 1]);
                    mma16816(sc[j], qh[jp], kl[nt * 2], kl[nt * 2 + 1]);
                }
            }
        }

        // ---- Mask (replace with -10000) ----
        const int row0 = wid * 16 + r0;
#pragma unroll
        for (int j = 0; j < 8; ++j) {
            __nv_bfloat162 m0v = *(const __nv_bfloat162*)(sB + row0 * FSTR + j * 8 + c2);
            __nv_bfloat162 m1v = *(const __nv_bfloat162*)(sB + (row0 + 8) * FSTR + j * 8 + c2);
            if (__low2float(m0v)  != 0.f) sc[j][0] = -10000.f;
            if (__high2float(m0v) != 0.f) sc[j][1] = -10000.f;
            if (__low2float(m1v)  != 0.f) sc[j][2] = -10000.f;
            if (__high2float(m1v) != 0.f) sc[j][3] = -10000.f;
        }

        // ---- Online softmax ----
        float mt0 = -1e30f, mt1 = -1e30f;
#pragma unroll
        for (int j = 0; j < 8; ++j) {
            mt0 = fmaxf(mt0, fmaxf(sc[j][0], sc[j][1]));
            mt1 = fmaxf(mt1, fmaxf(sc[j][2], sc[j][3]));
        }
        mt0 = fmaxf(mt0, __shfl_xor_sync(0xffffffffu, mt0, 1));
        mt0 = fmaxf(mt0, __shfl_xor_sync(0xffffffffu, mt0, 2));
        mt1 = fmaxf(mt1, __shfl_xor_sync(0xffffffffu, mt1, 1));
        mt1 = fmaxf(mt1, __shfl_xor_sync(0xffffffffu, mt1, 2));
        float mn0 = fmaxf(rm0, mt0), cf0 = fexp(rm0 - mn0);
        float mn1 = fmaxf(rm1, mt1), cf1 = fexp(rm1 - mn1);
        rm0 = mn0; rm1 = mn1;

        float rs0 = 0.f, rs1 = 0.f;
#pragma unroll
        for (int j = 0; j < 8; ++j) {
            sc[j][0] = fexp(sc[j][0] - mn0);
            sc[j][1] = fexp(sc[j][1] - mn0);
            sc[j][2] = fexp(sc[j][2] - mn1);
            sc[j][3] = fexp(sc[j][3] - mn1);
            rs0 += sc[j][0] + sc[j][1];
            rs1 += sc[j][2] + sc[j][3];
        }
        rs0 += __shfl_xor_sync(0xffffffffu, rs0, 1);
        rs0 += __shfl_xor_sync(0xffffffffu, rs0, 2);
        rs1 += __shfl_xor_sync(0xffffffffu, rs1, 1);
        rs1 += __shfl_xor_sync(0xffffffffu, rs1, 2);
        l0 = l0 * cf0 + rs0;
        l1 = l1 * cf1 + rs1;

#pragma unroll
        for (int jd = 0; jd < 8; ++jd) {
            o[jd][0] *= cf0; o[jd][1] *= cf0;
            o[jd][2] *= cf1; o[jd][3] *= cf1;
        }

        // ---- P -> A fragments in registers ----
        uint32_t ph[4][4], pl[4][4];
#pragma unroll
        for (int jp = 0; jp < 4; ++jp) {
            pack3(sc[2 * jp][0],     sc[2 * jp][1],     ph[jp][0], pl[jp][0]);
            pack3(sc[2 * jp][2],     sc[2 * jp][3],     ph[jp][1], pl[jp][1]);
            pack3(sc[2 * jp + 1][0], sc[2 * jp + 1][1], ph[jp][2], pl[jp][2]);
            pack3(sc[2 * jp + 1][2], sc[2 * jp + 1][3], ph[jp][3], pl[jp][3]);
        }

        // ---- O += P V (bf16x3) ----
#pragma unroll
        for (int np = 0; np < 4; ++np) {
#pragma unroll
            for (int jp = 0; jp < 4; ++jp) {
                uint32_t off = (uint32_t)(((np * 16 + b_n) * FSTR + jp * 16 + b_k) * 2);
                uint32_t vh[4], vl[4];
                ldsm4(uVh + off, vh);
                ldsm4(uVl + off, vl);
#pragma unroll
                for (int nt = 0; nt < 2; ++nt) {
                    int jd = np * 2 + nt;
                    mma16816(o[jd], ph[jp], vh[nt * 2], vh[nt * 2 + 1]);
                    mma16816(o[jd], pl[jp], vh[nt * 2], vh[nt * 2 + 1]);
                    mma16816(o[jd], ph[jp], vl[nt * 2], vl[nt * 2 + 1]);
                }
            }
        }
        __syncthreads();   // readers done before stage st is refilled
    }

    // ---- Epilogue: write bf16 hi/lo directly (fused decompose) ----
    float i0 = 1.f / l0, i1 = 1.f / l1;
    int qr = q0 + wid * 16 + r0;
#pragma unroll
    for (int jd = 0; jd < 8; ++jd) {
        uint32_t h01, l01, h23, l23;
        pack3(o[jd][0] * i0, o[jd][1] * i0, h01, l01);
        pack3(o[jd][2] * i1, o[jd][3] * i1, h23, l23);
        size_t base0 = ((size_t)b * SEQ + qr) * HIDD + h * HD + jd * 8 + c2;
        size_t base1 = base0 + (size_t)8 * HIDD;
        *(uint32_t*)&g_xhi[base0] = h01;
        *(uint32_t*)&g_xlo[base0] = l01;
        *(uint32_t*)&g_xhi[base1] = h23;
        *(uint32_t*)&g_xlo[base1] = l23;
    }
}

// ---------------------------------------------------------------------------
extern "C" void kernel_launch(void* const* d_in, const int* in_sizes, int n_in,
                              void* d_out, int out_size) {
    (void)in_sizes; (void)n_in; (void)out_size;
    const float* hidden        = (const float*)d_in[0];
    const unsigned char* mask  = (const unsigned char*)d_in[1];
    const int* pos             = (const int*)d_in[2];
    const float* Wqkv          = (const float*)d_in[3];
    const float* Wo            = (const float*)d_in[4];
    float* out                 = (float*)d_out;

    float* qkv = nullptr;
    __nv_bfloat16 *xhi, *xlo, *whi, *wlo;
    cudaGetSymbolAddress((void**)&qkv, g_qkv);
    cudaGetSymbolAddress((void**)&xhi, g_xhi);
    cudaGetSymbolAddress((void**)&xlo, g_xlo);
    cudaGetSymbolAddress((void**)&whi, g_whi);
    cudaGetSymbolAddress((void**)&wlo, g_wlo);

    cudaFuncSetAttribute(flash_hmma, cudaFuncAttributeMaxDynamicSharedMemorySize,
                         FLASH_SMEM);
    cudaFuncSetAttribute(hmma_gemm, cudaFuncAttributeMaxDynamicSharedMemorySize,
                         GEMM_SMEM);

    detect_mask_kernel<<<1, 256>>>(mask);
    mask_bias_kernel<<<(NB * SEQ * SEQ / 8) / 256, 256>>>(mask);

    // QKV projection
    decompose_kernel<<<(MROWS * HIDD / 4) / 256, 256>>>(
        (const float4*)hidden, (__nv_bfloat162*)xhi, (__nv_bfloat162*)xlo,
        MROWS * HIDD / 4);
    decompose_kernel<<<(NQKV * HIDD / 4) / 256, 256>>>(
        (const float4*)Wqkv, (__nv_bfloat162*)whi, (__nv_bfloat162*)wlo,
        NQKV * HIDD / 4);
    hmma_gemm<<<dim3(NQKV / 128, MROWS / 128), 256, GEMM_SMEM>>>(
        xhi, xlo, whi, wlo, qkv, HIDD, NQKV);

    rope_scatter<<<(NB * SEQ * NH * 32) / 256, 256>>>(qkv, pos);

    // Flash writes x hi/lo directly (fused decompose of attn)
    flash_hmma<<<dim3(SEQ / 64, NH, NB), 128, FLASH_SMEM>>>();

    // O projection
    decompose_kernel<<<(HIDD * HIDD / 4) / 256, 256>>>(
        (const float4*)Wo, (__nv_bfloat162*)whi, (__nv_bfloat162*)wlo,
        HIDD * HIDD / 4);
    hmma_gemm<<<dim3(HIDD / 128, MROWS / 128), 256, GEMM_SMEM>>>(
        xhi, xlo, whi, wlo, out, HIDD, HIDD);
}

// round 16
// speedup vs baseline: 1.0611x; 1.0611x over previous
#include <cuda_runtime.h>
#include <cuda_bf16.h>
#include <math.h>
#include <stdint.h>

#define SEQ   2048
#define NH    32
#define HD    64
#define HIDD  2048
#define NB    2
#define NQKV  (3 * NH * HD)   // 6144
#define MROWS (NB * SEQ)      // 4096

// ---------------------------------------------------------------------------
// Scratch (__device__ globals per harness rules — no cudaMalloc anywhere)
// ---------------------------------------------------------------------------
__device__ float g_qkv[(size_t)MROWS * NQKV];
__device__ int   g_mask_u8;
__device__ float g_biasf[(size_t)NB * SEQ * SEQ];            // 0 / -10000 mask bias
// GEMM decomposition buffers (x reused: hidden, then attn written by flash)
__device__ __nv_bfloat16 g_xhi[(size_t)MROWS * HIDD];
__device__ __nv_bfloat16 g_xlo[(size_t)MROWS * HIDD];
__device__ __nv_bfloat16 g_whi[(size_t)NQKV * HIDD];
__device__ __nv_bfloat16 g_wlo[(size_t)NQKV * HIDD];
// Attention operands, bf16 hi/lo
__device__ __nv_bfloat16 g_Qhi[(size_t)NB * NH * SEQ * HD];  // [B,H,S,D], scaled 1/8
__device__ __nv_bfloat16 g_Qlo[(size_t)NB * NH * SEQ * HD];
__device__ __nv_bfloat16 g_Khi[(size_t)NB * NH * SEQ * HD];
__device__ __nv_bfloat16 g_Klo[(size_t)NB * NH * SEQ * HD];
__device__ __nv_bfloat16 g_Vthi[(size_t)NB * NH * HD * SEQ]; // [B,H,D,S]
__device__ __nv_bfloat16 g_Vtlo[(size_t)NB * NH * HD * SEQ];

// ---------------------------------------------------------------------------
// Helpers (portable PTX: sm_80+)
// ---------------------------------------------------------------------------
__device__ __forceinline__ uint32_t smem_u32(const void* p) {
    uint32_t a;
    asm("{ .reg .u64 t; cvta.to.shared.u64 t, %1; cvt.u32.u64 %0, t; }"
        : "=r"(a) : "l"(p));
    return a;
}

__device__ __forceinline__ void ldsm4(uint32_t addr, uint32_t* r) {
    asm volatile("ldmatrix.sync.aligned.m8n8.x4.shared.b16 {%0,%1,%2,%3}, [%4];"
                 : "=r"(r[0]), "=r"(r[1]), "=r"(r[2]), "=r"(r[3]) : "r"(addr));
}

__device__ __forceinline__ void mma16816(float* c, const uint32_t* a,
                                         uint32_t b0, uint32_t b1) {
    asm volatile(
        "mma.sync.aligned.m16n8k16.row.col.f32.bf16.bf16.f32 "
        "{%0,%1,%2,%3}, {%4,%5,%6,%7}, {%8,%9}, {%0,%1,%2,%3};"
        : "+f"(c[0]), "+f"(c[1]), "+f"(c[2]), "+f"(c[3])
        : "r"(a[0]), "r"(a[1]), "r"(a[2]), "r"(a[3]), "r"(b0), "r"(b1));
}

__device__ __forceinline__ void cp16(uint32_t dst, const void* src) {
    asm volatile("cp.async.cg.shared.global [%0], [%1], 16;"
                 :: "r"(dst), "l"(src));
}

__device__ __forceinline__ float ex2f(float x) {
    float y;
    asm("ex2.approx.f32 %0, %1;" : "=f"(y) : "f"(x));
    return y;
}

#define L2E 1.4426950408889634f

// float pair -> bf16x2 hi reg + bf16x2 lo reg
__device__ __forceinline__ void pack3(float f0, float f1, uint32_t& rh, uint32_t& rl) {
    __nv_bfloat16 h0 = __float2bfloat16(f0), h1 = __float2bfloat16(f1);
    __nv_bfloat16 l0 = __float2bfloat16(f0 - __bfloat162float(h0));
    __nv_bfloat16 l1 = __float2bfloat16(f1 - __bfloat162float(h1));
    __nv_bfloat162 H = __halves2bfloat162(h0, h1);
    __nv_bfloat162 L = __halves2bfloat162(l0, l1);
    rh = *(uint32_t*)&H;
    rl = *(uint32_t*)&L;
}

// ---------------------------------------------------------------------------
// Decompose fp32 -> bf16 hi + lo
// ---------------------------------------------------------------------------
__global__ __launch_bounds__(256) void decompose_kernel(
        const float4* __restrict__ x, __nv_bfloat162* __restrict__ hi,
        __nv_bfloat162* __restrict__ lo, int n4) {
    int i = blockIdx.x * blockDim.x + threadIdx.x;
    if (i >= n4) return;
    float4 v = x[i];
    __nv_bfloat16 h0 = __float2bfloat16(v.x), h1 = __float2bfloat16(v.y);
    __nv_bfloat16 h2 = __float2bfloat16(v.z), h3 = __float2bfloat16(v.w);
    __nv_bfloat16 l0 = __float2bfloat16(v.x - __bfloat162float(h0));
    __nv_bfloat16 l1 = __float2bfloat16(v.y - __bfloat162float(h1));
    __nv_bfloat16 l2 = __float2bfloat16(v.z - __bfloat162float(h2));
    __nv_bfloat16 l3 = __float2bfloat16(v.w - __bfloat162float(h3));
    hi[2 * i]     = __halves2bfloat162(h0, h1);
    hi[2 * i + 1] = __halves2bfloat162(h2, h3);
    lo[2 * i]     = __halves2bfloat162(l0, l1);
    lo[2 * i + 1] = __halves2bfloat162(l2, l3);
}

// ---------------------------------------------------------------------------
// Mask detection + conversion to float 0/-10000 bias array
// ---------------------------------------------------------------------------
__global__ void detect_mask_kernel(const unsigned char* __restrict__ m) {
    __shared__ int found;
    if (threadIdx.x == 0) found = 0;
    __syncthreads();
    const uint4* p = (const uint4*)m;
    int f = 0;
    for (int i = threadIdx.x; i < 65536; i += blockDim.x) {
        uint4 w = p[i];
        unsigned ws[4] = {w.x, w.y, w.z, w.w};
#pragma unroll
        for (int j = 0; j < 4; ++j) {
            unsigned v = ws[j];
            if (((v >> 8) & 0xFFu) == 1u || ((v >> 16) & 0xFFu) == 1u ||
                ((v >> 24) & 0xFFu) == 1u)
                f = 1;
        }
    }
    if (f) atomicOr(&found, 1);
    __syncthreads();
    if (threadIdx.x == 0) g_mask_u8 = found;
}

__global__ __launch_bounds__(256) void mask_bias_kernel(const unsigned char* __restrict__ m) {
    const size_t i = ((size_t)blockIdx.x * blockDim.x + threadIdx.x) * 8;
    float o[8];
    if (g_mask_u8) {
        uint2 w = *(const uint2*)(m + i);
#pragma unroll
        for (int j = 0; j < 4; ++j) {
            o[j]     = ((w.x >> (j * 8)) & 0xFFu) ? -10000.f : 0.f;
            o[j + 4] = ((w.y >> (j * 8)) & 0xFFu) ? -10000.f : 0.f;
        }
    } else {
        const unsigned* p = (const unsigned*)m + i;
        uint4 w0 = *(const uint4*)p;
        uint4 w1 = *(const uint4*)(p + 4);
        o[0] = w0.x ? -10000.f : 0.f; o[1] = w0.y ? -10000.f : 0.f;
        o[2] = w0.z ? -10000.f : 0.f; o[3] = w0.w ? -10000.f : 0.f;
        o[4] = w1.x ? -10000.f : 0.f; o[5] = w1.y ? -10000.f : 0.f;
        o[6] = w1.z ? -10000.f : 0.f; o[7] = w1.w ? -10000.f : 0.f;
    }
    *(float4*)&g_biasf[i]     = make_float4(o[0], o[1], o[2], o[3]);
    *(float4*)&g_biasf[i + 4] = make_float4(o[4], o[5], o[6], o[7]);
}

// ---------------------------------------------------------------------------
// Projection GEMM (R14-proven): bf16x3 HMMA, cp.async 2-stage, BK=32.
// ---------------------------------------------------------------------------
#define SSTR 40
#define ARR_B  (128 * SSTR * 2)
#define STG_B  (4 * ARR_B)
#define GEMM_SMEM (2 * STG_B)   // 81920

__global__ __launch_bounds__(256, 2) void hmma_gemm(
        const __nv_bfloat16* __restrict__ Ah, const __nv_bfloat16* __restrict__ Al,
        const __nv_bfloat16* __restrict__ Bh, const __nv_bfloat16* __restrict__ Bl,
        float* __restrict__ C, int K, int N) {
    extern __shared__ char gsm[];
    const uint32_t ub = smem_u32(gsm);

    const int tid = threadIdx.x;
    const int wid = tid >> 5;
    const int lane = tid & 31;
    const int warp_m = wid & 1;
    const int warp_n = wid >> 1;
    const int m0 = blockIdx.y * 128, n0 = blockIdx.x * 128;

    const int lr = tid >> 1;
    const int ls = (tid & 1) << 4;
    const __nv_bfloat16* pAh = Ah + (size_t)(m0 + lr) * K + ls;
    const __nv_bfloat16* pAl = Al + (size_t)(m0 + lr) * K + ls;
    const __nv_bfloat16* pBh = Bh + (size_t)(n0 + lr) * K + ls;
    const __nv_bfloat16* pBl = Bl + (size_t)(n0 + lr) * K + ls;
    const uint32_t so = (uint32_t)(lr * SSTR + ls) * 2;

    const int a_row = lane & 15;
    const int a_col = (lane >> 4) << 3;
    const int b_n   = (lane & 7) + ((lane & 16) ? 8 : 0);
    const int b_k   = (lane & 8) ? 8 : 0;

    float acc[4][4][4];
#pragma unroll
    for (int i = 0; i < 4; ++i)
#pragma unroll
        for (int j = 0; j < 4; ++j)
#pragma unroll
            for (int v = 0; v < 4; ++v) acc[i][j][v] = 0.f;

    const int kIters = K >> 5;

    auto issue = [&](int it, int st) {
        const int k0 = it << 5;
        uint32_t d = ub + st * STG_B + so;
        cp16(d,                pAh + k0);
        cp16(d + 16,           pAh + k0 + 8);
        cp16(d + ARR_B,        pAl + k0);
        cp16(d + ARR_B + 16,   pAl + k0 + 8);
        cp16(d + 2 * ARR_B,      pBh + k0);
        cp16(d + 2 * ARR_B + 16, pBh + k0 + 8);
        cp16(d + 3 * ARR_B,      pBl + k0);
        cp16(d + 3 * ARR_B + 16, pBl + k0 + 8);
        asm volatile("cp.async.commit_group;" ::: "memory");
    };

    issue(0, 0);

    for (int it = 0; it < kIters; ++it) {
        const int st = it & 1;
        if (it + 1 < kIters) {
            issue(it + 1, st ^ 1);
            asm volatile("cp.async.wait_group 1;" ::: "memory");
        } else {
            asm volatile("cp.async.wait_group 0;" ::: "memory");
        }
        __syncthreads();

        const uint32_t uAh = ub + st * STG_B;
        const uint32_t uAl = uAh + ARR_B;
        const uint32_t uBh = uAh + 2 * ARR_B;
        const uint32_t uBl = uAh + 3 * ARR_B;

#pragma unroll
        for (int ks = 0; ks < 2; ++ks) {
            const int kb = ks << 4;
            uint32_t bh[2][4], bl[2][4];
#pragma unroll
            for (int np = 0; np < 2; ++np) {
                uint32_t boff = (uint32_t)(((warp_n * 32 + np * 16 + b_n) * SSTR
                                            + kb + b_k) * 2);
                ldsm4(uBh + boff, bh[np]);
                ldsm4(uBl + boff, bl[np]);
            }
#pragma unroll
            for (int mt = 0; mt < 4; ++mt) {
                uint32_t aoff = (uint32_t)(((warp_m * 64 + mt * 16 + a_row) * SSTR
                                            + kb + a_col) * 2);
                uint32_t ahf[4], alf[4];
                ldsm4(uAh + aoff, ahf);
                ldsm4(uAl + aoff, alf);
#pragma unroll
                for (int nt = 0; nt < 4; ++nt) {
                    uint32_t b0h = bh[nt >> 1][(nt & 1) * 2];
                    uint32_t b1h = bh[nt >> 1][(nt & 1) * 2 + 1];
                    uint32_t b0l = bl[nt >> 1][(nt & 1) * 2];
                    uint32_t b1l = bl[nt >> 1][(nt & 1) * 2 + 1];
                    mma16816(acc[mt][nt], ahf, b0h, b1h);
                    mma16816(acc[mt][nt], alf, b0h, b1h);
                    mma16816(acc[mt][nt], ahf, b0l, b1l);
                }
            }
        }
        __syncthreads();
    }

#pragma unroll
    for (int mt = 0; mt < 4; ++mt) {
#pragma unroll
        for (int nt = 0; nt < 4; ++nt) {
            int r = m0 + warp_m * 64 + mt * 16 + (lane >> 2);
            int c = n0 + warp_n * 32 + nt * 8 + (lane & 3) * 2;
            float2 lo = make_float2(acc[mt][nt][0], acc[mt][nt][1]);
            float2 hi = make_float2(acc[mt][nt][2], acc[mt][nt][3]);
            *(float2*)(C + (size_t)r * N + c) = lo;
            *(float2*)(C + (size_t)(r + 8) * N + c) = hi;
        }
    }
}

// ---------------------------------------------------------------------------
// RoPE + split + bf16 hi/lo decomposition. Q scaled by 1/8. V transposed.
// ---------------------------------------------------------------------------
__device__ __forceinline__ void wr_hl(__nv_bfloat16* hi, __nv_bfloat16* lo,
                                      size_t off, float v) {
    __nv_bfloat16 h = __float2bfloat16(v);
    hi[off] = h;
    lo[off] = __float2bfloat16(v - __bfloat162float(h));
}

__global__ __launch_bounds__(256) void rope_scatter(const float* __restrict__ qkv,
                                                    const int* __restrict__ pos_ids) {
    int idx = blockIdx.x * blockDim.x + threadIdx.x;
    int d = idx & 31;
    int h = (idx >> 5) & (NH - 1);
    int s = (idx >> 10) & (SEQ - 1);
    int b = idx >> 21;
    int pos = pos_ids[b * SEQ + s];

    const float* src = qkv + (size_t)(b * SEQ + s) * NQKV + h * (3 * HD);
    float q1 = src[d],       q2 = src[d + 32];
    float k1 = src[64 + d],  k2 = src[96 + d];
    float v1 = src[128 + d], v2 = src[160 + d];

    float invf = (float)pow(10000.0, -(double)d / 32.0);
    float t = (float)pos * invf;
    float sn = (float)sin((double)t);
    float cs = (float)cos((double)t);

    const float qs = 0.125f;
    size_t qk = ((size_t)(b * NH + h) * SEQ + s) * HD;
    wr_hl(g_Qhi, g_Qlo, qk + d,      (q1 * cs - q2 * sn) * qs);
    wr_hl(g_Qhi, g_Qlo, qk + d + 32, (q2 * cs + q1 * sn) * qs);
    wr_hl(g_Khi, g_Klo, qk + d,      k1 * cs - k2 * sn);
    wr_hl(g_Khi, g_Klo, qk + d + 32, k2 * cs + k1 * sn);
    size_t vt = ((size_t)(b * NH + h) * HD + d) * SEQ + s;
    wr_hl(g_Vthi, g_Vtlo, vt,                 v1);
    wr_hl(g_Vthi, g_Vtlo, vt + 32 * SEQ,      v2);
}

// ---------------------------------------------------------------------------
// Flash attention via bf16x3 HMMA. Block = (b, h, 64 q rows), 4 warps x m16.
// Mask folded into accumulator init (float bias in smem). cp.async staging,
// single-buffered to preserve 4 CTAs/SM. exp via ex2.approx.
// ---------------------------------------------------------------------------
#define FSTR 72
#define AF_B (64 * FSTR * 2)                   // 9216
#define FLASH_SMEM (4 * AF_B + 64 * 72 * 4)    // 55296

__global__ __launch_bounds__(128) void flash_hmma() {
    extern __shared__ char fsm[];
    const uint32_t ufb = smem_u32(fsm);
    const uint32_t uKh = ufb;
    const uint32_t uKl = ufb + AF_B;
    const uint32_t uVh = ufb + 2 * AF_B;
    const uint32_t uVl = ufb + 3 * AF_B;
    float* sBias = (float*)(fsm + 4 * AF_B);
    const uint32_t uBias = ufb + 4 * AF_B;

    const int q0 = blockIdx.x * 64;
    const int h  = blockIdx.y;
    const int b  = blockIdx.z;
    const int tid = threadIdx.x;
    const int wid = tid >> 5;
    const int lane = tid & 31;

    const size_t hb = (size_t)(b * NH + h) * SEQ;
    const size_t vb = (size_t)(b * NH + h) * HD;

    const int lrow = tid >> 1;
    const int lhalf = (tid & 1) * 32;

    // ---- Stage Q tile, ldsm Q fragments ----
    {
        const __nv_bfloat16* qh_src = g_Qhi + (hb + q0 + lrow) * HD + lhalf;
        const __nv_bfloat16* ql_src = g_Qlo + (hb + q0 + lrow) * HD + lhalf;
        __nv_bfloat16* dh = (__nv_bfloat16*)fsm + lrow * FSTR + lhalf;
        __nv_bfloat16* dl = (__nv_bfloat16*)(fsm + AF_B) + lrow * FSTR + lhalf;
#pragma unroll
        for (int j = 0; j < 4; ++j) {
            *(uint4*)(dh + j * 8) = *(const uint4*)(qh_src + j * 8);
            *(uint4*)(dl + j * 8) = *(const uint4*)(ql_src + j * 8);
        }
    }
    __syncthreads();

    const int a_row = lane & 15;
    const int a_col = (lane >> 4) << 3;
    const int b_n   = (lane & 7) + ((lane & 16) ? 8 : 0);
    const int b_k   = (lane & 8) ? 8 : 0;

    uint32_t qh[4][4], ql[4][4];
#pragma unroll
    for (int kc = 0; kc < 4; ++kc) {
        uint32_t off = (uint32_t)(((wid * 16 + a_row) * FSTR + kc * 16 + a_col) * 2);
        ldsm4(uKh + off, qh[kc]);
        ldsm4(uKl + off, ql[kc]);
    }

    const int r0 = lane >> 2;
    const int c2 = (lane & 3) * 2;
    const int row0 = wid * 16 + r0;

    float rm0 = -1e30f, rm1 = -1e30f, l0 = 0.f, l1 = 0.f;
    float o[8][4];
#pragma unroll
    for (int jd = 0; jd < 8; ++jd)
#pragma unroll
        for (int v = 0; v < 4; ++v) o[jd][v] = 0.f;

    const uint32_t soKV = (uint32_t)(lrow * FSTR + lhalf) * 2;
    const uint32_t soB  = (uint32_t)(lrow * 72 + lhalf) * 4;

    for (int it = 0; it < SEQ / 64; ++it) {
        __syncthreads();   // readers of previous tile (and Q frags) done
        {
            const int k0 = it << 6;
            const __nv_bfloat16* kh = g_Khi + (hb + k0 + lrow) * HD + lhalf;
            const __nv_bfloat16* kl = g_Klo + (hb + k0 + lrow) * HD + lhalf;
            const __nv_bfloat16* vh = g_Vthi + (vb + lrow) * SEQ + k0 + lhalf;
            const __nv_bfloat16* vl = g_Vtlo + (vb + lrow) * SEQ + k0 + lhalf;
            const float* bi = g_biasf + ((size_t)b * SEQ + q0 + lrow) * SEQ + k0 + lhalf;
#pragma unroll
            for (int j = 0; j < 4; ++j) {
                cp16(uKh + soKV + j * 16, kh + j * 8);
                cp16(uKl + soKV + j * 16, kl + j * 8);
                cp16(uVh + soKV + j * 16, vh + j * 8);
                cp16(uVl + soKV + j * 16, vl + j * 8);
            }
#pragma unroll
            for (int j = 0; j < 8; ++j)
                cp16(uBias + soB + j * 16, bi + j * 4);
            asm volatile("cp.async.commit_group;" ::: "memory");
            asm volatile("cp.async.wait_group 0;" ::: "memory");
        }
        __syncthreads();

        // ---- S = bias + Q K^T (bf16x3); mask folded into accumulator ----
        float sc[8][4];
#pragma unroll
        for (int j = 0; j < 8; ++j) {
            float2 b0 = *(const float2*)(sBias + row0 * 72 + j * 8 + c2);
            float2 b1 = *(const float2*)(sBias + (row0 + 8) * 72 + j * 8 + c2);
            sc[j][0] = b0.x; sc[j][1] = b0.y;
            sc[j][2] = b1.x; sc[j][3] = b1.y;
        }
#pragma unroll
        for (int jp = 0; jp < 4; ++jp) {
#pragma unroll
            for (int np = 0; np < 4; ++np) {
                uint32_t off = (uint32_t)(((np * 16 + b_n) * FSTR + jp * 16 + b_k) * 2);
                uint32_t kh[4], kl[4];
                ldsm4(uKh + off, kh);
                ldsm4(uKl + off, kl);
#pragma unroll
                for (int nt = 0; nt < 2; ++nt) {
                    int j = np * 2 + nt;
                    mma16816(sc[j], qh[jp], kh[nt * 2], kh[nt * 2 + 1]);
                    mma16816(sc[j], ql[jp], kh[nt * 2], kh[nt * 2 + 1]);
                    mma16816(sc[j], qh[jp], kl[nt * 2], kl[nt * 2 + 1]);
                }
            }
        }

        // ---- Online softmax (ex2-based exp) ----
        float mt0 = -1e30f, mt1 = -1e30f;
#pragma unroll
        for (int j = 0; j < 8; ++j) {
            mt0 = fmaxf(mt0, fmaxf(sc[j][0], sc[j][1]));
            mt1 = fmaxf(mt1, fmaxf(sc[j][2], sc[j][3]));
        }
        mt0 = fmaxf(mt0, __shfl_xor_sync(0xffffffffu, mt0, 1));
        mt0 = fmaxf(mt0, __shfl_xor_sync(0xffffffffu, mt0, 2));
        mt1 = fmaxf(mt1, __shfl_xor_sync(0xffffffffu, mt1, 1));
        mt1 = fmaxf(mt1, __shfl_xor_sync(0xffffffffu, mt1, 2));
        float mn0 = fmaxf(rm0, mt0);
        float mn1 = fmaxf(rm1, mt1);
        float nm0 = -mn0 * L2E;
        float nm1 = -mn1 * L2E;
        float cf0 = ex2f(fmaf(rm0, L2E, nm0));
        float cf1 = ex2f(fmaf(rm1, L2E, nm1));
        rm0 = mn0; rm1 = mn1;

        float rs0 = 0.f, rs1 = 0.f;
#pragma unroll
        for (int j = 0; j < 8; ++j) {
            sc[j][0] = ex2f(fmaf(sc[j][0], L2E, nm0));
            sc[j][1] = ex2f(fmaf(sc[j][1], L2E, nm0));
            sc[j][2] = ex2f(fmaf(sc[j][2], L2E, nm1));
            sc[j][3] = ex2f(fmaf(sc[j][3], L2E, nm1));
            rs0 += sc[j][0] + sc[j][1];
            rs1 += sc[j][2] + sc[j][3];
        }
        rs0 += __shfl_xor_sync(0xffffffffu, rs0, 1);
        rs0 += __shfl_xor_sync(0xffffffffu, rs0, 2);
        rs1 += __shfl_xor_sync(0xffffffffu, rs1, 1);
        rs1 += __shfl_xor_sync(0xffffffffu, rs1, 2);
        l0 = l0 * cf0 + rs0;
        l1 = l1 * cf1 + rs1;

#pragma unroll
        for (int jd = 0; jd < 8; ++jd) {
            o[jd][0] *= cf0; o[jd][1] *= cf0;
            o[jd][2] *= cf1; o[jd][3] *= cf1;
        }

        // ---- P -> A fragments in registers ----
        uint32_t ph[4][4], pl[4][4];
#pragma unroll
        for (int jp = 0; jp < 4; ++jp) {
            pack3(sc[2 * jp][0],     sc[2 * jp][1],     ph[jp][0], pl[jp][0]);
            pack3(sc[2 * jp][2],     sc[2 * jp][3],     ph[jp][1], pl[jp][1]);
            pack3(sc[2 * jp + 1][0], sc[2 * jp + 1][1], ph[jp][2], pl[jp][2]);
            pack3(sc[2 * jp + 1][2], sc[2 * jp + 1][3], ph[jp][3], pl[jp][3]);
        }

        // ---- O += P V (bf16x3) ----
#pragma unroll
        for (int np = 0; np < 4; ++np) {
#pragma unroll
            for (int jp = 0; jp < 4; ++jp) {
                uint32_t off = (uint32_t)(((np * 16 + b_n) * FSTR + jp * 16 + b_k) * 2);
                uint32_t vh[4], vl[4];
                ldsm4(uVh + off, vh);
                ldsm4(uVl + off, vl);
#pragma unroll
                for (int nt = 0; nt < 2; ++nt) {
                    int jd = np * 2 + nt;
                    mma16816(o[jd], ph[jp], vh[nt * 2], vh[nt * 2 + 1]);
                    mma16816(o[jd], pl[jp], vh[nt * 2], vh[nt * 2 + 1]);
                    mma16816(o[jd], ph[jp], vl[nt * 2], vl[nt * 2 + 1]);
                }
            }
        }
    }

    // ---- Epilogue: write bf16 hi/lo directly (fused decompose) ----
    float i0 = 1.f / l0, i1 = 1.f / l1;
    int qr = q0 + wid * 16 + r0;
#pragma unroll
    for (int jd = 0; jd < 8; ++jd) {
        uint32_t h01, l01, h23, l23;
        pack3(o[jd][0] * i0, o[jd][1] * i0, h01, l01);
        pack3(o[jd][2] * i1, o[jd][3] * i1, h23, l23);
        size_t base0 = ((size_t)b * SEQ + qr) * HIDD + h * HD + jd * 8 + c2;
        size_t base1 = base0 + (size_t)8 * HIDD;
        *(uint32_t*)&g_xhi[base0] = h01;
        *(uint32_t*)&g_xlo[base0] = l01;
        *(uint32_t*)&g_xhi[base1] = h23;
        *(uint32_t*)&g_xlo[base1] = l23;
    }
}

// ---------------------------------------------------------------------------
extern "C" void kernel_launch(void* const* d_in, const int* in_sizes, int n_in,
                              void* d_out, int out_size) {
    (void)in_sizes; (void)n_in; (void)out_size;
    const float* hidden        = (const float*)d_in[0];
    const unsigned char* mask  = (const unsigned char*)d_in[1];
    const int* pos             = (const int*)d_in[2];
    const float* Wqkv          = (const float*)d_in[3];
    const float* Wo            = (const float*)d_in[4];
    float* out                 = (float*)d_out;

    float* qkv = nullptr;
    __nv_bfloat16 *xhi, *xlo, *whi, *wlo;
    cudaGetSymbolAddress((void**)&qkv, g_qkv);
    cudaGetSymbolAddress((void**)&xhi, g_xhi);
    cudaGetSymbolAddress((void**)&xlo, g_xlo);
    cudaGetSymbolAddress((void**)&whi, g_whi);
    cudaGetSymbolAddress((void**)&wlo, g_wlo);

    cudaFuncSetAttribute(flash_hmma, cudaFuncAttributeMaxDynamicSharedMemorySize,
                         FLASH_SMEM);
    cudaFuncSetAttribute(hmma_gemm, cudaFuncAttributeMaxDynamicSharedMemorySize,
                         GEMM_SMEM);

    detect_mask_kernel<<<1, 256>>>(mask);
    mask_bias_kernel<<<(NB * SEQ * SEQ / 8) / 256, 256>>>(mask);

    // QKV projection
    decompose_kernel<<<(MROWS * HIDD / 4) / 256, 256>>>(
        (const float4*)hidden, (__nv_bfloat162*)xhi, (__nv_bfloat162*)xlo,
        MROWS * HIDD / 4);
    decompose_kernel<<<(NQKV * HIDD / 4) / 256, 256>>>(
        (const float4*)Wqkv, (__nv_bfloat162*)whi, (__nv_bfloat162*)wlo,
        NQKV * HIDD / 4);
    hmma_gemm<<<dim3(NQKV / 128, MROWS / 128), 256, GEMM_SMEM>>>(
        xhi, xlo, whi, wlo, qkv, HIDD, NQKV);

    rope_scatter<<<(NB * SEQ * NH * 32) / 256, 256>>>(qkv, pos);

    // Flash writes x hi/lo directly (fused decompose of attn)
    flash_hmma<<<dim3(SEQ / 64, NH, NB), 128, FLASH_SMEM>>>();

    // O projection
    decompose_kernel<<<(HIDD * HIDD / 4) / 256, 256>>>(
        (const float4*)Wo, (__nv_bfloat162*)whi, (__nv_bfloat162*)wlo,
        HIDD * HIDD / 4);
    hmma_gemm<<<dim3(HIDD / 128, MROWS / 128), 256, GEMM_SMEM>>>(
        xhi, xlo, whi, wlo, out, HIDD, HIDD);
}

// round 17
// speedup vs baseline: 1.4866x; 1.4009x over previous
#include <cuda_runtime.h>
#include <cuda_bf16.h>
#include <math.h>
#include <stdint.h>

#define SEQ   2048
#define NH    32
#define HD    64
#define HIDD  2048
#define NB    2
#define NQKV  (3 * NH * HD)   // 6144
#define MROWS (NB * SEQ)      // 4096

// ---------------------------------------------------------------------------
// Scratch (__device__ globals per harness rules — no cudaMalloc anywhere)
// ---------------------------------------------------------------------------
__device__ float g_qkv[(size_t)MROWS * NQKV];
__device__ int   g_mask_u8;
__device__ float g_biasf[(size_t)NB * SEQ * SEQ];            // 0 / -10000 mask bias
__device__ float g_sint[2048 * 32];
__device__ float g_cost[2048 * 32];
// GEMM decomposition buffers (x reused: hidden, then attn written by flash)
__device__ __nv_bfloat16 g_xhi[(size_t)MROWS * HIDD];
__device__ __nv_bfloat16 g_xlo[(size_t)MROWS * HIDD];
__device__ __nv_bfloat16 g_whi[(size_t)NQKV * HIDD];
__device__ __nv_bfloat16 g_wlo[(size_t)NQKV * HIDD];
// Attention operands, bf16 hi/lo
__device__ __nv_bfloat16 g_Qhi[(size_t)NB * NH * SEQ * HD];  // [B,H,S,D], scaled 1/8
__device__ __nv_bfloat16 g_Qlo[(size_t)NB * NH * SEQ * HD];
__device__ __nv_bfloat16 g_Khi[(size_t)NB * NH * SEQ * HD];
__device__ __nv_bfloat16 g_Klo[(size_t)NB * NH * SEQ * HD];
__device__ __nv_bfloat16 g_Vthi[(size_t)NB * NH * HD * SEQ]; // [B,H,D,S]
__device__ __nv_bfloat16 g_Vtlo[(size_t)NB * NH * HD * SEQ];

// ---------------------------------------------------------------------------
// Helpers (portable PTX: sm_80+)
// ---------------------------------------------------------------------------
__device__ __forceinline__ uint32_t smem_u32(const void* p) {
    uint32_t a;
    asm("{ .reg .u64 t; cvta.to.shared.u64 t, %1; cvt.u32.u64 %0, t; }"
        : "=r"(a) : "l"(p));
    return a;
}

__device__ __forceinline__ void ldsm4(uint32_t addr, uint32_t* r) {
    asm volatile("ldmatrix.sync.aligned.m8n8.x4.shared.b16 {%0,%1,%2,%3}, [%4];"
                 : "=r"(r[0]), "=r"(r[1]), "=r"(r[2]), "=r"(r[3]) : "r"(addr));
}

__device__ __forceinline__ void mma16816(float* c, const uint32_t* a,
                                         uint32_t b0, uint32_t b1) {
    asm volatile(
        "mma.sync.aligned.m16n8k16.row.col.f32.bf16.bf16.f32 "
        "{%0,%1,%2,%3}, {%4,%5,%6,%7}, {%8,%9}, {%0,%1,%2,%3};"
        : "+f"(c[0]), "+f"(c[1]), "+f"(c[2]), "+f"(c[3])
        : "r"(a[0]), "r"(a[1]), "r"(a[2]), "r"(a[3]), "r"(b0), "r"(b1));
}

__device__ __forceinline__ void cp16(uint32_t dst, const void* src) {
    asm volatile("cp.async.cg.shared.global [%0], [%1], 16;"
                 :: "r"(dst), "l"(src));
}

__device__ __forceinline__ float ex2f(float x) {
    float y;
    asm("ex2.approx.f32 %0, %1;" : "=f"(y) : "f"(x));
    return y;
}

#define L2E 1.4426950408889634f

// float pair -> bf16x2 hi reg + bf16x2 lo reg
__device__ __forceinline__ void pack3(float f0, float f1, uint32_t& rh, uint32_t& rl) {
    __nv_bfloat16 h0 = __float2bfloat16(f0), h1 = __float2bfloat16(f1);
    __nv_bfloat16 l0 = __float2bfloat16(f0 - __bfloat162float(h0));
    __nv_bfloat16 l1 = __float2bfloat16(f1 - __bfloat162float(h1));
    __nv_bfloat162 H = __halves2bfloat162(h0, h1);
    __nv_bfloat162 L = __halves2bfloat162(l0, l1);
    rh = *(uint32_t*)&H;
    rl = *(uint32_t*)&L;
}

// ---------------------------------------------------------------------------
// One-time RoPE sin/cos table (fp64-accurate, fp32-rounded angles)
// ---------------------------------------------------------------------------
__global__ __launch_bounds__(256) void rope_table_kernel() {
    int i = blockIdx.x * blockDim.x + threadIdx.x;   // 65536
    int d = i & 31, pos = i >> 5;
    double invf = pow(10000.0, -(double)d / 32.0);
    float t = (float)pos * (float)invf;
    g_sint[i] = (float)sin((double)t);
    g_cost[i] = (float)cos((double)t);
}

// ---------------------------------------------------------------------------
// Decompose fp32 -> bf16 hi + lo
// ---------------------------------------------------------------------------
__global__ __launch_bounds__(256) void decompose_kernel(
        const float4* __restrict__ x, __nv_bfloat162* __restrict__ hi,
        __nv_bfloat162* __restrict__ lo, int n4) {
    int i = blockIdx.x * blockDim.x + threadIdx.x;
    if (i >= n4) return;
    float4 v = x[i];
    __nv_bfloat16 h0 = __float2bfloat16(v.x), h1 = __float2bfloat16(v.y);
    __nv_bfloat16 h2 = __float2bfloat16(v.z), h3 = __float2bfloat16(v.w);
    __nv_bfloat16 l0 = __float2bfloat16(v.x - __bfloat162float(h0));
    __nv_bfloat16 l1 = __float2bfloat16(v.y - __bfloat162float(h1));
    __nv_bfloat16 l2 = __float2bfloat16(v.z - __bfloat162float(h2));
    __nv_bfloat16 l3 = __float2bfloat16(v.w - __bfloat162float(h3));
    hi[2 * i]     = __halves2bfloat162(h0, h1);
    hi[2 * i + 1] = __halves2bfloat162(h2, h3);
    lo[2 * i]     = __halves2bfloat162(l0, l1);
    lo[2 * i + 1] = __halves2bfloat162(l2, l3);
}

// ---------------------------------------------------------------------------
// Mask detection + conversion to float 0/-10000 bias array
// ---------------------------------------------------------------------------
__global__ void detect_mask_kernel(const unsigned char* __restrict__ m) {
    __shared__ int found;
    if (threadIdx.x == 0) found = 0;
    __syncthreads();
    const uint4* p = (const uint4*)m;
    int f = 0;
    for (int i = threadIdx.x; i < 65536; i += blockDim.x) {
        uint4 w = p[i];
        unsigned ws[4] = {w.x, w.y, w.z, w.w};
#pragma unroll
        for (int j = 0; j < 4; ++j) {
            unsigned v = ws[j];
            if (((v >> 8) & 0xFFu) == 1u || ((v >> 16) & 0xFFu) == 1u ||
                ((v >> 24) & 0xFFu) == 1u)
                f = 1;
        }
    }
    if (f) atomicOr(&found, 1);
    __syncthreads();
    if (threadIdx.x == 0) g_mask_u8 = found;
}

__global__ __launch_bounds__(256) void mask_bias_kernel(const unsigned char* __restrict__ m) {
    const size_t i = ((size_t)blockIdx.x * blockDim.x + threadIdx.x) * 8;
    float o[8];
    if (g_mask_u8) {
        uint2 w = *(const uint2*)(m + i);
#pragma unroll
        for (int j = 0; j < 4; ++j) {
            o[j]     = ((w.x >> (j * 8)) & 0xFFu) ? -10000.f : 0.f;
            o[j + 4] = ((w.y >> (j * 8)) & 0xFFu) ? -10000.f : 0.f;
        }
    } else {
        const unsigned* p = (const unsigned*)m + i;
        uint4 w0 = *(const uint4*)p;
        uint4 w1 = *(const uint4*)(p + 4);
        o[0] = w0.x ? -10000.f : 0.f; o[1] = w0.y ? -10000.f : 0.f;
        o[2] = w0.z ? -10000.f : 0.f; o[3] = w0.w ? -10000.f : 0.f;
        o[4] = w1.x ? -10000.f : 0.f; o[5] = w1.y ? -10000.f : 0.f;
        o[6] = w1.z ? -10000.f : 0.f; o[7] = w1.w ? -10000.f : 0.f;
    }
    *(float4*)&g_biasf[i]     = make_float4(o[0], o[1], o[2], o[3]);
    *(float4*)&g_biasf[i + 4] = make_float4(o[4], o[5], o[6], o[7]);
}

// ---------------------------------------------------------------------------
// Projection GEMM (R14-proven): bf16x3 HMMA, cp.async 2-stage, BK=32.
// ---------------------------------------------------------------------------
#define SSTR 40
#define ARR_B  (128 * SSTR * 2)
#define STG_B  (4 * ARR_B)
#define GEMM_SMEM (2 * STG_B)   // 81920

__global__ __launch_bounds__(256, 2) void hmma_gemm(
        const __nv_bfloat16* __restrict__ Ah, const __nv_bfloat16* __restrict__ Al,
        const __nv_bfloat16* __restrict__ Bh, const __nv_bfloat16* __restrict__ Bl,
        float* __restrict__ C, int K, int N) {
    extern __shared__ char gsm[];
    const uint32_t ub = smem_u32(gsm);

    const int tid = threadIdx.x;
    const int wid = tid >> 5;
    const int lane = tid & 31;
    const int warp_m = wid & 1;
    const int warp_n = wid >> 1;
    const int m0 = blockIdx.y * 128, n0 = blockIdx.x * 128;

    const int lr = tid >> 1;
    const int ls = (tid & 1) << 4;
    const __nv_bfloat16* pAh = Ah + (size_t)(m0 + lr) * K + ls;
    const __nv_bfloat16* pAl = Al + (size_t)(m0 + lr) * K + ls;
    const __nv_bfloat16* pBh = Bh + (size_t)(n0 + lr) * K + ls;
    const __nv_bfloat16* pBl = Bl + (size_t)(n0 + lr) * K + ls;
    const uint32_t so = (uint32_t)(lr * SSTR + ls) * 2;

    const int a_row = lane & 15;
    const int a_col = (lane >> 4) << 3;
    const int b_n   = (lane & 7) + ((lane & 16) ? 8 : 0);
    const int b_k   = (lane & 8) ? 8 : 0;

    float acc[4][4][4];
#pragma unroll
    for (int i = 0; i < 4; ++i)
#pragma unroll
        for (int j = 0; j < 4; ++j)
#pragma unroll
            for (int v = 0; v < 4; ++v) acc[i][j][v] = 0.f;

    const int kIters = K >> 5;

    auto issue = [&](int it, int st) {
        const int k0 = it << 5;
        uint32_t d = ub + st * STG_B + so;
        cp16(d,                pAh + k0);
        cp16(d + 16,           pAh + k0 + 8);
        cp16(d + ARR_B,        pAl + k0);
        cp16(d + ARR_B + 16,   pAl + k0 + 8);
        cp16(d + 2 * ARR_B,      pBh + k0);
        cp16(d + 2 * ARR_B + 16, pBh + k0 + 8);
        cp16(d + 3 * ARR_B,      pBl + k0);
        cp16(d + 3 * ARR_B + 16, pBl + k0 + 8);
        asm volatile("cp.async.commit_group;" ::: "memory");
    };

    issue(0, 0);

    for (int it = 0; it < kIters; ++it) {
        const int st = it & 1;
        if (it + 1 < kIters) {
            issue(it + 1, st ^ 1);
            asm volatile("cp.async.wait_group 1;" ::: "memory");
        } else {
            asm volatile("cp.async.wait_group 0;" ::: "memory");
        }
        __syncthreads();

        const uint32_t uAh = ub + st * STG_B;
        const uint32_t uAl = uAh + ARR_B;
        const uint32_t uBh = uAh + 2 * ARR_B;
        const uint32_t uBl = uAh + 3 * ARR_B;

#pragma unroll
        for (int ks = 0; ks < 2; ++ks) {
            const int kb = ks << 4;
            uint32_t bh[2][4], bl[2][4];
#pragma unroll
            for (int np = 0; np < 2; ++np) {
                uint32_t boff = (uint32_t)(((warp_n * 32 + np * 16 + b_n) * SSTR
                                            + kb + b_k) * 2);
                ldsm4(uBh + boff, bh[np]);
                ldsm4(uBl + boff, bl[np]);
            }
#pragma unroll
            for (int mt = 0; mt < 4; ++mt) {
                uint32_t aoff = (uint32_t)(((warp_m * 64 + mt * 16 + a_row) * SSTR
                                            + kb + a_col) * 2);
                uint32_t ahf[4], alf[4];
                ldsm4(uAh + aoff, ahf);
                ldsm4(uAl + aoff, alf);
#pragma unroll
                for (int nt = 0; nt < 4; ++nt) {
                    uint32_t b0h = bh[nt >> 1][(nt & 1) * 2];
                    uint32_t b1h = bh[nt >> 1][(nt & 1) * 2 + 1];
                    uint32_t b0l = bl[nt >> 1][(nt & 1) * 2];
                    uint32_t b1l = bl[nt >> 1][(nt & 1) * 2 + 1];
                    mma16816(acc[mt][nt], ahf, b0h, b1h);
                    mma16816(acc[mt][nt], alf, b0h, b1h);
                    mma16816(acc[mt][nt], ahf, b0l, b1l);
                }
            }
        }
        __syncthreads();
    }

#pragma unroll
    for (int mt = 0; mt < 4; ++mt) {
#pragma unroll
        for (int nt = 0; nt < 4; ++nt) {
            int r = m0 + warp_m * 64 + mt * 16 + (lane >> 2);
            int c = n0 + warp_n * 32 + nt * 8 + (lane & 3) * 2;
            float2 lo = make_float2(acc[mt][nt][0], acc[mt][nt][1]);
            float2 hi = make_float2(acc[mt][nt][2], acc[mt][nt][3]);
            *(float2*)(C + (size_t)r * N + c) = lo;
            *(float2*)(C + (size_t)(r + 8) * N + c) = hi;
        }
    }
}

// ---------------------------------------------------------------------------
// RoPE + split + bf16 hi/lo decomposition (table-based sin/cos).
// ---------------------------------------------------------------------------
__device__ __forceinline__ void wr_hl(__nv_bfloat16* hi, __nv_bfloat16* lo,
                                      size_t off, float v) {
    __nv_bfloat16 h = __float2bfloat16(v);
    hi[off] = h;
    lo[off] = __float2bfloat16(v - __bfloat162float(h));
}

__global__ __launch_bounds__(256) void rope_scatter(const float* __restrict__ qkv,
                                                    const int* __restrict__ pos_ids) {
    int idx = blockIdx.x * blockDim.x + threadIdx.x;
    int d = idx & 31;
    int h = (idx >> 5) & (NH - 1);
    int s = (idx >> 10) & (SEQ - 1);
    int b = idx >> 21;
    int pos = pos_ids[b * SEQ + s];

    const float* src = qkv + (size_t)(b * SEQ + s) * NQKV + h * (3 * HD);
    float q1 = src[d],       q2 = src[d + 32];
    float k1 = src[64 + d],  k2 = src[96 + d];
    float v1 = src[128 + d], v2 = src[160 + d];

    int ti = (pos & 2047) * 32 + d;
    float sn = g_sint[ti];
    float cs = g_cost[ti];

    const float qs = 0.125f;
    size_t qk = ((size_t)(b * NH + h) * SEQ + s) * HD;
    wr_hl(g_Qhi, g_Qlo, qk + d,      (q1 * cs - q2 * sn) * qs);
    wr_hl(g_Qhi, g_Qlo, qk + d + 32, (q2 * cs + q1 * sn) * qs);
    wr_hl(g_Khi, g_Klo, qk + d,      k1 * cs - k2 * sn);
    wr_hl(g_Khi, g_Klo, qk + d + 32, k2 * cs + k1 * sn);
    size_t vt = ((size_t)(b * NH + h) * HD + d) * SEQ + s;
    wr_hl(g_Vthi, g_Vtlo, vt,                 v1);
    wr_hl(g_Vthi, g_Vtlo, vt + 32 * SEQ,      v2);
}

// ---------------------------------------------------------------------------
// Flash attention via bf16x3 HMMA, 2-stage cp.async double buffer (lean stage:
// K/V hi/lo only; bias loaded straight to registers). 3 CTAs/SM.
// Grid: (head, q-tile, batch) so the concurrent wave shares bias rows and K/V.
// ---------------------------------------------------------------------------
#define FSTR 72
#define AF_B (64 * FSTR * 2)       // 9216
#define STGF_B (4 * AF_B)          // 36864
#define FLASH_SMEM (2 * STGF_B)    // 73728

__global__ __launch_bounds__(128) void flash_hmma() {
    extern __shared__ char fsm[];
    const uint32_t ufb = smem_u32(fsm);

    const int h  = blockIdx.x;
    const int q0 = blockIdx.y * 64;
    const int b  = blockIdx.z;
    const int tid = threadIdx.x;
    const int wid = tid >> 5;
    const int lane = tid & 31;

    const size_t hb = (size_t)(b * NH + h) * SEQ;
    const size_t vb = (size_t)(b * NH + h) * HD;

    const int lrow = tid >> 1;
    const int lhalf = (tid & 1) * 32;

    // ---- Stage Q tile (stage-0 Kh/Kl region), ldsm Q fragments ----
    {
        const __nv_bfloat16* qh_src = g_Qhi + (hb + q0 + lrow) * HD + lhalf;
        const __nv_bfloat16* ql_src = g_Qlo + (hb + q0 + lrow) * HD + lhalf;
        __nv_bfloat16* dh = (__nv_bfloat16*)fsm + lrow * FSTR + lhalf;
        __nv_bfloat16* dl = (__nv_bfloat16*)(fsm + AF_B) + lrow * FSTR + lhalf;
#pragma unroll
        for (int j = 0; j < 4; ++j) {
            *(uint4*)(dh + j * 8) = *(const uint4*)(qh_src + j * 8);
            *(uint4*)(dl + j * 8) = *(const uint4*)(ql_src + j * 8);
        }
    }
    __syncthreads();

    const int a_row = lane & 15;
    const int a_col = (lane >> 4) << 3;
    const int b_n   = (lane & 7) + ((lane & 16) ? 8 : 0);
    const int b_k   = (lane & 8) ? 8 : 0;

    uint32_t qh[4][4], ql[4][4];
#pragma unroll
    for (int kc = 0; kc < 4; ++kc) {
        uint32_t off = (uint32_t)(((wid * 16 + a_row) * FSTR + kc * 16 + a_col) * 2);
        ldsm4(ufb + off, qh[kc]);
        ldsm4(ufb + AF_B + off, ql[kc]);
    }
    __syncthreads();   // Q frag reads done; stage 0 free for cp.async

    const int r0 = lane >> 2;
    const int c2 = (lane & 3) * 2;
    const int row0 = wid * 16 + r0;
    const float* biasRow0 = g_biasf + ((size_t)b * SEQ + q0 + row0) * SEQ;
    const float* biasRow1 = biasRow0 + (size_t)8 * SEQ;

    float rm0 = -1e30f, rm1 = -1e30f, l0 = 0.f, l1 = 0.f;
    float o[8][4];
#pragma unroll
    for (int jd = 0; jd < 8; ++jd)
#pragma unroll
        for (int v = 0; v < 4; ++v) o[jd][v] = 0.f;

    const uint32_t soKV = (uint32_t)(lrow * FSTR + lhalf) * 2;

    auto issue_f = [&](int it, int st) {
        const int k0 = it << 6;
        const __nv_bfloat16* kh = g_Khi + (hb + k0 + lrow) * HD + lhalf;
        const __nv_bfloat16* kl = g_Klo + (hb + k0 + lrow) * HD + lhalf;
        const __nv_bfloat16* vh = g_Vthi + (vb + lrow) * SEQ + k0 + lhalf;
        const __nv_bfloat16* vl = g_Vtlo + (vb + lrow) * SEQ + k0 + lhalf;
        uint32_t d = ufb + st * STGF_B + soKV;
#pragma unroll
        for (int j = 0; j < 4; ++j) {
            cp16(d + j * 16,             kh + j * 8);
            cp16(d + AF_B + j * 16,      kl + j * 8);
            cp16(d + 2 * AF_B + j * 16,  vh + j * 8);
            cp16(d + 3 * AF_B + j * 16,  vl + j * 8);
        }
        asm volatile("cp.async.commit_group;" ::: "memory");
    };

    issue_f(0, 0);

    const int nTiles = SEQ / 64;
    for (int it = 0; it < nTiles; ++it) {
        const int st = it & 1;
        if (it + 1 < nTiles) {
            issue_f(it + 1, st ^ 1);
            asm volatile("cp.async.wait_group 1;" ::: "memory");
        } else {
            asm volatile("cp.async.wait_group 0;" ::: "memory");
        }
        __syncthreads();

        const int k0 = it << 6;
        const uint32_t uKh = ufb + st * STGF_B;
        const uint32_t uKl = uKh + AF_B;
        const uint32_t uVh = uKh + 2 * AF_B;
        const uint32_t uVl = uKh + 3 * AF_B;

        // ---- Issue bias loads early (consumed after the QK MMAs) ----
        float2 bb0[8], bb1[8];
#pragma unroll
        for (int j = 0; j < 8; ++j) {
            bb0[j] = *(const float2*)(biasRow0 + k0 + j * 8 + c2);
            bb1[j] = *(const float2*)(biasRow1 + k0 + j * 8 + c2);
        }

        // ---- S = Q K^T (bf16x3) ----
        float sc[8][4];
#pragma unroll
        for (int j = 0; j < 8; ++j)
#pragma unroll
            for (int v = 0; v < 4; ++v) sc[j][v] = 0.f;
#pragma unroll
        for (int jp = 0; jp < 4; ++jp) {
#pragma unroll
            for (int np = 0; np < 4; ++np) {
                uint32_t off = (uint32_t)(((np * 16 + b_n) * FSTR + jp * 16 + b_k) * 2);
                uint32_t kh[4], kl[4];
                ldsm4(uKh + off, kh);
                ldsm4(uKl + off, kl);
#pragma unroll
                for (int nt = 0; nt < 2; ++nt) {
                    int j = np * 2 + nt;
                    mma16816(sc[j], qh[jp], kh[nt * 2], kh[nt * 2 + 1]);
                    mma16816(sc[j], ql[jp], kh[nt * 2], kh[nt * 2 + 1]);
                    mma16816(sc[j], qh[jp], kl[nt * 2], kl[nt * 2 + 1]);
                }
            }
        }

        // ---- Add mask bias ----
#pragma unroll
        for (int j = 0; j < 8; ++j) {
            sc[j][0] += bb0[j].x; sc[j][1] += bb0[j].y;
            sc[j][2] += bb1[j].x; sc[j][3] += bb1[j].y;
        }

        // ---- Online softmax (ex2) ----
        float mt0 = -1e30f, mt1 = -1e30f;
#pragma unroll
        for (int j = 0; j < 8; ++j) {
            mt0 = fmaxf(mt0, fmaxf(sc[j][0], sc[j][1]));
            mt1 = fmaxf(mt1, fmaxf(sc[j][2], sc[j][3]));
        }
        mt0 = fmaxf(mt0, __shfl_xor_sync(0xffffffffu, mt0, 1));
        mt0 = fmaxf(mt0, __shfl_xor_sync(0xffffffffu, mt0, 2));
        mt1 = fmaxf(mt1, __shfl_xor_sync(0xffffffffu, mt1, 1));
        mt1 = fmaxf(mt1, __shfl_xor_sync(0xffffffffu, mt1, 2));
        float mn0 = fmaxf(rm0, mt0);
        float mn1 = fmaxf(rm1, mt1);
        float nm0 = -mn0 * L2E;
        float nm1 = -mn1 * L2E;
        float cf0 = ex2f(fmaf(rm0, L2E, nm0));
        float cf1 = ex2f(fmaf(rm1, L2E, nm1));
        rm0 = mn0; rm1 = mn1;

        float rs0 = 0.f, rs1 = 0.f;
#pragma unroll
        for (int j = 0; j < 8; ++j) {
            sc[j][0] = ex2f(fmaf(sc[j][0], L2E, nm0));
            sc[j][1] = ex2f(fmaf(sc[j][1], L2E, nm0));
            sc[j][2] = ex2f(fmaf(sc[j][2], L2E, nm1));
            sc[j][3] = ex2f(fmaf(sc[j][3], L2E, nm1));
            rs0 += sc[j][0] + sc[j][1];
            rs1 += sc[j][2] + sc[j][3];
        }
        rs0 += __shfl_xor_sync(0xffffffffu, rs0, 1);
        rs0 += __shfl_xor_sync(0xffffffffu, rs0, 2);
        rs1 += __shfl_xor_sync(0xffffffffu, rs1, 1);
        rs1 += __shfl_xor_sync(0xffffffffu, rs1, 2);
        l0 = l0 * cf0 + rs0;
        l1 = l1 * cf1 + rs1;

#pragma unroll
        for (int jd = 0; jd < 8; ++jd) {
            o[jd][0] *= cf0; o[jd][1] *= cf0;
            o[jd][2] *= cf1; o[jd][3] *= cf1;
        }

        // ---- P -> A fragments in registers ----
        uint32_t ph[4][4], pl[4][4];
#pragma unroll
        for (int jp = 0; jp < 4; ++jp) {
            pack3(sc[2 * jp][0],     sc[2 * jp][1],     ph[jp][0], pl[jp][0]);
            pack3(sc[2 * jp][2],     sc[2 * jp][3],     ph[jp][1], pl[jp][1]);
            pack3(sc[2 * jp + 1][0], sc[2 * jp + 1][1], ph[jp][2], pl[jp][2]);
            pack3(sc[2 * jp + 1][2], sc[2 * jp + 1][3], ph[jp][3], pl[jp][3]);
        }

        // ---- O += P V (bf16x3) ----
#pragma unroll
        for (int np = 0; np < 4; ++np) {
#pragma unroll
            for (int jp = 0; jp < 4; ++jp) {
                uint32_t off = (uint32_t)(((np * 16 + b_n) * FSTR + jp * 16 + b_k) * 2);
                uint32_t vh[4], vl[4];
                ldsm4(uVh + off, vh);
                ldsm4(uVl + off, vl);
#pragma unroll
                for (int nt = 0; nt < 2; ++nt) {
                    int jd = np * 2 + nt;
                    mma16816(o[jd], ph[jp], vh[nt * 2], vh[nt * 2 + 1]);
                    mma16816(o[jd], pl[jp], vh[nt * 2], vh[nt * 2 + 1]);
                    mma16816(o[jd], ph[jp], vl[nt * 2], vl[nt * 2 + 1]);
                }
            }
        }
        __syncthreads();   // stage st readers done before refill at it+2
    }

    // ---- Epilogue: write bf16 hi/lo directly (fused decompose) ----
    float i0 = 1.f / l0, i1 = 1.f / l1;
    int qr = q0 + wid * 16 + r0;
#pragma unroll
    for (int jd = 0; jd < 8; ++jd) {
        uint32_t h01, l01, h23, l23;
        pack3(o[jd][0] * i0, o[jd][1] * i0, h01, l01);
        pack3(o[jd][2] * i1, o[jd][3] * i1, h23, l23);
        size_t base0 = ((size_t)b * SEQ + qr) * HIDD + h * HD + jd * 8 + c2;
        size_t base1 = base0 + (size_t)8 * HIDD;
        *(uint32_t*)&g_xhi[base0] = h01;
        *(uint32_t*)&g_xlo[base0] = l01;
        *(uint32_t*)&g_xhi[base1] = h23;
        *(uint32_t*)&g_xlo[base1] = l23;
    }
}

// ---------------------------------------------------------------------------
extern "C" void kernel_launch(void* const* d_in, const int* in_sizes, int n_in,
                              void* d_out, int out_size) {
    (void)in_sizes; (void)n_in; (void)out_size;
    const float* hidden        = (const float*)d_in[0];
    const unsigned char* mask  = (const unsigned char*)d_in[1];
    const int* pos             = (const int*)d_in[2];
    const float* Wqkv          = (const float*)d_in[3];
    const float* Wo            = (const float*)d_in[4];
    float* out                 = (float*)d_out;

    float* qkv = nullptr;
    __nv_bfloat16 *xhi, *xlo, *whi, *wlo;
    cudaGetSymbolAddress((void**)&qkv, g_qkv);
    cudaGetSymbolAddress((void**)&xhi, g_xhi);
    cudaGetSymbolAddress((void**)&xlo, g_xlo);
    cudaGetSymbolAddress((void**)&whi, g_whi);
    cudaGetSymbolAddress((void**)&wlo, g_wlo);

    cudaFuncSetAttribute(flash_hmma, cudaFuncAttributeMaxDynamicSharedMemorySize,
                         FLASH_SMEM);
    cudaFuncSetAttribute(hmma_gemm, cudaFuncAttributeMaxDynamicSharedMemorySize,
                         GEMM_SMEM);

    rope_table_kernel<<<256, 256>>>();
    detect_mask_kernel<<<1, 256>>>(mask);
    mask_bias_kernel<<<(NB * SEQ * SEQ / 8) / 256, 256>>>(mask);

    // QKV projection
    decompose_kernel<<<(MROWS * HIDD / 4) / 256, 256>>>(
        (const float4*)hidden, (__nv_bfloat162*)xhi, (__nv_bfloat162*)xlo,
        MROWS * HIDD / 4);
    decompose_kernel<<<(NQKV * HIDD / 4) / 256, 256>>>(
        (const float4*)Wqkv, (__nv_bfloat162*)whi, (__nv_bfloat162*)wlo,
        NQKV * HIDD / 4);
    hmma_gemm<<<dim3(NQKV / 128, MROWS / 128), 256, GEMM_SMEM>>>(
        xhi, xlo, whi, wlo, qkv, HIDD, NQKV);

    rope_scatter<<<(NB * SEQ * NH * 32) / 256, 256>>>(qkv, pos);

    // Flash writes x hi/lo directly (fused decompose of attn)
    flash_hmma<<<dim3(NH, SEQ / 64, NB), 128, FLASH_SMEM>>>();

    // O projection
    decompose_kernel<<<(HIDD * HIDD / 4) / 256, 256>>>(
        (const float4*)Wo, (__nv_bfloat162*)whi, (__nv_bfloat162*)wlo,
        HIDD * HIDD / 4);
    hmma_gemm<<<dim3(HIDD / 128, MROWS / 128), 256, GEMM_SMEM>>>(
        xhi, xlo, whi, wlo, out, HIDD, HIDD);
}